// round 1
// baseline (speedup 1.0000x reference)
#include <cuda_runtime.h>
#include <cuda_bf16.h>

// AttentionRouting: u [B=4, I=32, N=32, J=16, H=32, W=32] f32, bias b [1,32,32,1,1,1]
//   v = sum_i u                         [B,N,J,H,W]
//   c_raw[b,i,n,h,w] = sum_j u * v
//   c = softmax_n(c_raw * 0.25) + b[i,n]
//   s[b,n,j,h,w] = sum_i u * c
//   squash over j: s *= (1 - 1/(exp(|s|)+eps)) / (|s|+eps)
//
// Plan: K1 fuses v+c_raw per (b,n,h) slice (64KB smem), K2 computes per-pixel
// log-sum-exp, K3 computes s + squash reading u once more. u read 2x total.

#define BB 4
#define II 32
#define NN 32
#define JJ 16
#define HH 32
#define WW 32
#define HW 1024
// stride between consecutive i in u (elements): N*J*H*W
#define STRIDE_I 524288
// slice row count: I*J
#define ROWS 512

// scratch: c_raw [B,I,N,H,W] = 4*32*32*1024 floats (16 MB)
__device__ float g_craw[BB * II * NN * HW];
// lse [B,I,H,W] = 131072 floats (0.5 MB)
__device__ float g_lse[BB * II * HW];

// ---------------------------------------------------------------------------
// K1: per (b, n, h) slice. 256 threads. dynamic smem: u_s[512][32] = 64KB.
// Computes v (during load, register partials) and c_raw, writes c_raw.
// ---------------------------------------------------------------------------
__global__ void __launch_bounds__(256) k1_craw(const float* __restrict__ u) {
    extern __shared__ float u_s[];                 // [ROWS][32], 64 KB
    __shared__ float4 vpart[256];                  // 4 KB
    __shared__ float v_s[JJ * WW];                 // 2 KB

    const int bid = blockIdx.x;                    // ((b*NN + n)*HH + h)
    const int h = bid & 31;
    const int n = (bid >> 5) & 31;
    const int b = bid >> 10;
    const int tid = threadIdx.x;

    // element base for (b, n, h): ((b*II + i)*NN + n)*JJ*HW + j*HW + h*WW + w
    const int base = (b * 1024 + n) * (JJ * HW) + h * WW;

    // --- load slice, accumulating partial v in registers ---
    // thread covers: j = (tid>>3)&15, q = tid&7 (float4 within w-row),
    //                i = 2k + (tid>>7), k=0..15  (even or odd i set)
    const int j = (tid >> 3) & 15;
    const int q = tid & 7;
    const int ihalf = tid >> 7;

    float4 vp = make_float4(0.f, 0.f, 0.f, 0.f);
#pragma unroll
    for (int k = 0; k < 16; k++) {
        const int i = 2 * k + ihalf;
        const float4 val =
            *(const float4*)(u + base + i * STRIDE_I + j * HW + q * 4);
        *(float4*)(&u_s[(i * JJ + j) * WW + q * 4]) = val;
        vp.x += val.x; vp.y += val.y; vp.z += val.z; vp.w += val.w;
    }
    vpart[tid] = vp;
    __syncthreads();

    // combine even/odd i halves -> v[j][w]
    if (tid < 128) {
        const float4 a = vpart[tid];
        const float4 c4 = vpart[tid + 128];
        float4 r;
        r.x = a.x + c4.x; r.y = a.y + c4.y; r.z = a.z + c4.z; r.w = a.w + c4.w;
        *(float4*)(&v_s[j * WW + q * 4]) = r;      // tid<128 -> same (j,q)
    }
    __syncthreads();

    // --- c_raw[i][w] = sum_j u_s[i][j][w] * v[j][w], v held in registers ---
    const int w = tid & 31;
    const int i0 = tid >> 5;                       // 0..7
    float vreg[JJ];
#pragma unroll
    for (int jj = 0; jj < JJ; jj++) vreg[jj] = v_s[jj * WW + w];

#pragma unroll
    for (int m = 0; m < 4; m++) {
        const int i = i0 + m * 8;
        float acc = 0.f;
#pragma unroll
        for (int jj = 0; jj < JJ; jj++)
            acc += u_s[(i * JJ + jj) * WW + w] * vreg[jj];
        g_craw[((b * II + i) * NN + n) * HW + h * WW + w] = acc;
    }
}

// ---------------------------------------------------------------------------
// K2: per-pixel (b,i,h,w) log-sum-exp over n of 0.25*c_raw.
// ---------------------------------------------------------------------------
__global__ void __launch_bounds__(256) k2_lse() {
    const int t = blockIdx.x * 256 + threadIdx.x;  // 0..131071
    const int hw = t & 1023;
    const int bi = t >> 10;                        // b*II + i
    const float* p = g_craw + bi * (NN * HW) + hw;

    float vals[NN];
    float m = -3.402823466e+38f;
#pragma unroll
    for (int n = 0; n < NN; n++) {
        vals[n] = 0.25f * p[n * HW];
        m = fmaxf(m, vals[n]);
    }
    float s = 0.f;
#pragma unroll
    for (int n = 0; n < NN; n++) s += expf(vals[n] - m);
    g_lse[t] = m + logf(s);
}

// ---------------------------------------------------------------------------
// K3: per (b, n, h) slice, 512 threads (j,w).
// c[i,w] = exp(0.25*c_raw - lse) + bias[i,n]; s[j,w] = sum_i u*c; squash.
// ---------------------------------------------------------------------------
__global__ void __launch_bounds__(512) k3_out(const float* __restrict__ u,
                                             const float* __restrict__ bias,
                                             float* __restrict__ out) {
    __shared__ float c_s[II * WW];                 // 4 KB
    __shared__ float s_s[JJ * WW];                 // 2 KB

    const int bid = blockIdx.x;
    const int h = bid & 31;
    const int n = (bid >> 5) & 31;
    const int b = bid >> 10;
    const int tid = threadIdx.x;

    // prologue: c_s[i*32+w]
#pragma unroll
    for (int t = tid; t < II * WW; t += 512) {
        const int i = t >> 5;
        const int w = t & 31;
        const int hw = h * WW + w;
        const float cr = g_craw[((b * II + i) * NN + n) * HW + hw];
        const float lse = g_lse[(b * II + i) * HW + hw];
        c_s[t] = expf(0.25f * cr - lse) + __ldg(&bias[i * NN + n]);
    }
    __syncthreads();

    const int jj = tid >> 5;                       // 0..15
    const int w = tid & 31;
    const int base = (b * 1024 + n) * (JJ * HW) + h * WW + w + jj * HW;

    float a0 = 0.f, a1 = 0.f, a2 = 0.f, a3 = 0.f;
#pragma unroll
    for (int i = 0; i < II; i += 4) {
        a0 += u[base + (i + 0) * STRIDE_I] * c_s[(i + 0) * 32 + w];
        a1 += u[base + (i + 1) * STRIDE_I] * c_s[(i + 1) * 32 + w];
        a2 += u[base + (i + 2) * STRIDE_I] * c_s[(i + 2) * 32 + w];
        a3 += u[base + (i + 3) * STRIDE_I] * c_s[(i + 3) * 32 + w];
    }
    const float acc = (a0 + a1) + (a2 + a3);

    s_s[tid] = acc;
    __syncthreads();

    // squash over j (each thread redundantly reduces its column w)
    float nrm2 = 0.f;
#pragma unroll
    for (int j2 = 0; j2 < JJ; j2++) {
        const float x = s_s[j2 * WW + w];
        nrm2 += x * x;
    }
    const float nrm = sqrtf(nrm2);
    const float factor =
        (1.0f - 1.0f / (expf(nrm) + 1e-20f)) / (nrm + 1e-20f);

    out[((b * NN + n) * JJ + jj) * HW + h * WW + w] = acc * factor;
}

// ---------------------------------------------------------------------------
extern "C" void kernel_launch(void* const* d_in, const int* in_sizes, int n_in,
                              void* d_out, int out_size) {
    const float* u = (const float*)d_in[0];       // 67,108,864 elems
    const float* bias = (const float*)d_in[1];    // 1,024 elems
    float* out = (float*)d_out;                   // 2,097,152 elems

    cudaFuncSetAttribute(k1_craw, cudaFuncAttributeMaxDynamicSharedMemorySize,
                         ROWS * WW * (int)sizeof(float));  // 64 KB

    const int grid_slices = BB * NN * HH;          // 4096
    k1_craw<<<grid_slices, 256, ROWS * WW * sizeof(float)>>>(u);
    k2_lse<<<(BB * II * HW) / 256, 256>>>();       // 512 blocks
    k3_out<<<grid_slices, 512>>>(u, bias, out);
}